// round 1
// baseline (speedup 1.0000x reference)
#include <cuda_runtime.h>
#include <cfloat>

// Problem constants (fixed shapes from reference)
#define DDIM   64          // vector dim
#define KCODE  512         // codebook size
#define KP     256         // code pairs
#define NTOT   8388608     // total enc elements = B*C*H*W
#define NVEC   131072      // number of D-dim vectors
#define TPB    512
#define NBLK   (NVEC / TPB)   // 256

// dynamic smem layout:
//   float2 s_e[DDIM][KP]      : 64*256*8   = 131072 B   (-2*embed, pair-interleaved)
//   float2 s_esq[KP]          : 256*8      =   2048 B   (||e||^2 pairs)
//   double s_red[16]          :              128 B
#define SME_BYTES   (DDIM * KP * 8)
#define SESQ_BYTES  (KP * 8)
#define SMEM_BYTES  (SME_BYTES + SESQ_BYTES + 16 * 8)

__device__ double g_loss_sum;

__global__ void vq_zero_kernel() { g_loss_sum = 0.0; }

__global__ void vq_finalize_kernel(float* out, int out_size) {
    if (out_size >= NTOT + 1) {
        out[NTOT] = (float)(2.0 * g_loss_sum / (double)NTOT);
    }
}

__device__ __forceinline__ unsigned long long ffma2(unsigned long long a,
                                                    unsigned long long b,
                                                    unsigned long long c) {
    unsigned long long d;
    asm("fma.rn.f32x2 %0, %1, %2, %3;" : "=l"(d) : "l"(a), "l"(b), "l"(c));
    return d;
}

__device__ __forceinline__ unsigned long long pack2(float v) {
    unsigned long long r;
    asm("mov.b64 %0, {%1, %1};" : "=l"(r) : "r"(__float_as_uint(v)));
    return r;
}

__global__ __launch_bounds__(TPB, 1)
void vq_main_kernel(const float* __restrict__ enc,
                    const float* __restrict__ embed,
                    float* __restrict__ out,
                    int out_size) {
    extern __shared__ unsigned char sraw[];
    float2* s_e   = (float2*)sraw;                                   // [DDIM][KP]
    float2* s_esq = (float2*)(sraw + SME_BYTES);                     // [KP]
    double* s_red = (double*)(sraw + SME_BYTES + SESQ_BYTES);        // [16]
    const unsigned long long* s_esq_u = (const unsigned long long*)s_esq;

    const int tid = threadIdx.x;

    // ---- cooperative codebook load: s_e[d*KP + p] = {-2*E[2p][d], -2*E[2p+1][d]}
    for (int idx = tid; idx < DDIM * KP; idx += TPB) {
        int d = idx >> 8;          // / KP
        int p = idx & (KP - 1);
        float a = embed[(2 * p) * DDIM + d];
        float b = embed[(2 * p + 1) * DDIM + d];
        s_e[idx] = make_float2(-2.0f * a, -2.0f * b);
    }
    // ---- esq pairs
    if (tid < KP) {
        float s0 = 0.f, s1 = 0.f;
        const float* e0 = embed + (2 * tid) * DDIM;
        const float* e1 = e0 + DDIM;
#pragma unroll
        for (int d = 0; d < DDIM; d++) {
            s0 += e0[d] * e0[d];
            s1 += e1[d] * e1[d];
        }
        s_esq[tid] = make_float2(s0, s1);
    }
    __syncthreads();

    // ---- load this thread's vector (one vector per thread)
    const int v = blockIdx.x * TPB + tid;
    float x[DDIM];
    {
        const float4* xp = (const float4*)(enc + (size_t)v * DDIM);
#pragma unroll
        for (int i = 0; i < DDIM / 4; i++) {
            float4 t = xp[i];
            x[4 * i + 0] = t.x; x[4 * i + 1] = t.y;
            x[4 * i + 2] = t.z; x[4 * i + 3] = t.w;
        }
    }

    // ---- argmin over 512 codes, 16 codes (8 pairs) per chunk, packed f32x2 FMA
    float best = FLT_MAX;
    int bi = 0;
#pragma unroll 1
    for (int p0 = 0; p0 < KP; p0 += 8) {
        unsigned long long acc[8];
#pragma unroll
        for (int j = 0; j < 8; j++) acc[j] = s_esq_u[p0 + j];

#pragma unroll
        for (int d = 0; d < DDIM; d++) {
            unsigned long long x2 = pack2(x[d]);
            const ulonglong2* row = (const ulonglong2*)(s_e + d * KP + p0);
            ulonglong2 t0 = row[0];   // pairs p0+0, p0+1   (LDS.128 broadcast)
            ulonglong2 t1 = row[1];
            ulonglong2 t2 = row[2];
            ulonglong2 t3 = row[3];
            acc[0] = ffma2(x2, t0.x, acc[0]);
            acc[1] = ffma2(x2, t0.y, acc[1]);
            acc[2] = ffma2(x2, t1.x, acc[2]);
            acc[3] = ffma2(x2, t1.y, acc[3]);
            acc[4] = ffma2(x2, t2.x, acc[4]);
            acc[5] = ffma2(x2, t2.y, acc[5]);
            acc[6] = ffma2(x2, t3.x, acc[6]);
            acc[7] = ffma2(x2, t3.y, acc[7]);
        }
#pragma unroll
        for (int j = 0; j < 8; j++) {
            float d0 = __uint_as_float((unsigned)(acc[j] & 0xFFFFFFFFull));
            float d1 = __uint_as_float((unsigned)(acc[j] >> 32));
            int k0 = 2 * (p0 + j);
            if (d0 < best) { best = d0; bi = k0; }
            if (d1 < best) { best = d1; bi = k0 + 1; }
        }
    }

    // ---- gather quantized vector, write output, accumulate loss
    float lsum = 0.f;
    {
        const int pw = bi >> 1;
        const int hi = bi & 1;
        float* op = out + (size_t)v * DDIM;
#pragma unroll
        for (int d = 0; d < DDIM; d++) {
            float2 ee = s_e[d * KP + pw];
            float e = -0.5f * (hi ? ee.y : ee.x);   // undo the -2 folding (exact)
            float diff = e - x[d];
            lsum += diff * diff;
            op[d] = e;
        }
    }
    if (out_size >= NTOT + 1 + NVEC) {
        out[NTOT + 1 + v] = (float)bi;              // closest indices as fp32
    }

    // ---- block reduce loss -> global double accumulator
    double ls = (double)lsum;
#pragma unroll
    for (int off = 16; off > 0; off >>= 1)
        ls += __shfl_down_sync(0xffffffffu, ls, off);
    if ((tid & 31) == 0) s_red[tid >> 5] = ls;
    __syncthreads();
    if (tid == 0) {
        double s = 0.0;
#pragma unroll
        for (int i = 0; i < TPB / 32; i++) s += s_red[i];
        atomicAdd(&g_loss_sum, s);
    }
}

extern "C" void kernel_launch(void* const* d_in, const int* in_sizes, int n_in,
                              void* d_out, int out_size) {
    const float* enc   = (const float*)d_in[0];   // (32,64,64,64) fp32
    const float* embed = (const float*)d_in[1];   // (512,64)      fp32
    float* out = (float*)d_out;

    static bool attr_set = false;
    if (!attr_set) {
        cudaFuncSetAttribute(vq_main_kernel,
                             cudaFuncAttributeMaxDynamicSharedMemorySize,
                             SMEM_BYTES);
        attr_set = true;
    }

    vq_zero_kernel<<<1, 1>>>();
    vq_main_kernel<<<NBLK, TPB, SMEM_BYTES>>>(enc, embed, out, out_size);
    vq_finalize_kernel<<<1, 1>>>(out, out_size);
}

// round 2
// speedup vs baseline: 1.5933x; 1.5933x over previous
#include <cuda_runtime.h>
#include <cfloat>

// Shapes (fixed): enc (32,64,64,64) fp32 -> 131072 vectors of D=64; codebook (512,64) fp32.
#define DDIM   64
#define KCODE  512
#define KP     256            // code pairs
#define NTOT   8388608
#define NVEC   131072
#define TPB    256
#define GRID   148
#define VPU    64             // vectors per work unit (one warp, 2 per lane)
#define NUNITS (NVEC / VPU)   // 2048

// smem: float2 s_e[DDIM][KP] (codebook, -2*E, pair-interleaved) + float2 s_esq[KP]
#define SME_BYTES   (DDIM * KP * 8)     // 131072
#define SESQ_BYTES  (KP * 8)            // 2048
#define SMEM_BYTES  (SME_BYTES + SESQ_BYTES)

__device__ double       g_loss = 0.0;
__device__ unsigned int g_unit = 0;
__device__ unsigned int g_done = 0;

__device__ __forceinline__ unsigned long long ffma2(unsigned long long a,
                                                    unsigned long long b,
                                                    unsigned long long c) {
    unsigned long long d;
    asm("fma.rn.f32x2 %0, %1, %2, %3;" : "=l"(d) : "l"(a), "l"(b), "l"(c));
    return d;
}

__device__ __forceinline__ unsigned long long pack2(float v) {
    unsigned long long r;
    asm("mov.b64 %0, {%1, %1};" : "=l"(r) : "r"(__float_as_uint(v)));
    return r;
}

__device__ __forceinline__ float lo32(unsigned long long a) {
    return __uint_as_float((unsigned)a);
}
__device__ __forceinline__ float hi32(unsigned long long a) {
    return __uint_as_float((unsigned)(a >> 32));
}

__global__ __launch_bounds__(TPB, 1)
void vq_kernel(const float* __restrict__ enc,
               const float* __restrict__ embed,
               float* __restrict__ out,
               int out_size) {
    extern __shared__ unsigned char sraw[];
    float2* s_e   = (float2*)sraw;                        // [DDIM][KP]
    float2* s_esq = (float2*)(sraw + SME_BYTES);          // [KP]
    const unsigned long long* s_esq_u = (const unsigned long long*)s_esq;

    const int tid  = threadIdx.x;
    const int lane = tid & 31;

    // ---- codebook -> smem: s_e[d*KP+p] = {-2*E[2p][d], -2*E[2p+1][d]}
    for (int idx = tid; idx < DDIM * KP; idx += TPB) {
        int d = idx >> 8;
        int p = idx & (KP - 1);
        float a = embed[(2 * p) * DDIM + d];
        float b = embed[(2 * p + 1) * DDIM + d];
        s_e[idx] = make_float2(-2.0f * a, -2.0f * b);
    }
    // ---- ||e||^2 pairs
    if (tid < KP) {
        float s0 = 0.f, s1 = 0.f;
        const float* e0 = embed + (2 * tid) * DDIM;
        const float* e1 = e0 + DDIM;
#pragma unroll
        for (int d = 0; d < DDIM; d++) { s0 += e0[d] * e0[d]; s1 += e1[d] * e1[d]; }
        s_esq[tid] = make_float2(s0, s1);
    }
    __syncthreads();

    float lsum = 0.f;

    // ---- persistent warp work-stealing over 64-vector units
    for (;;) {
        unsigned u;
        if (lane == 0) u = atomicAdd(&g_unit, 1u);
        u = __shfl_sync(0xffffffffu, u, 0);
        if (u >= NUNITS) break;

        const int v0 = (int)u * VPU + 2 * lane;   // this lane's two vectors
        const int v1 = v0 + 1;

        float x0[DDIM], x1[DDIM];
        {
            const float4* xp = (const float4*)(enc + (size_t)v0 * DDIM);
#pragma unroll
            for (int i = 0; i < DDIM / 4; i++) {
                float4 t = xp[i];
                x0[4*i+0] = t.x; x0[4*i+1] = t.y; x0[4*i+2] = t.z; x0[4*i+3] = t.w;
            }
            xp = (const float4*)(enc + (size_t)v1 * DDIM);
#pragma unroll
            for (int i = 0; i < DDIM / 4; i++) {
                float4 t = xp[i];
                x1[4*i+0] = t.x; x1[4*i+1] = t.y; x1[4*i+2] = t.z; x1[4*i+3] = t.w;
            }
        }

        float best0 = FLT_MAX, best1 = FLT_MAX;
        int   bi0 = 0, bi1 = 0;

#pragma unroll 1
        for (int p0 = 0; p0 < KP; p0 += 4) {     // 8 codes per chunk
            unsigned long long a00 = s_esq_u[p0 + 0];
            unsigned long long a01 = s_esq_u[p0 + 1];
            unsigned long long a02 = s_esq_u[p0 + 2];
            unsigned long long a03 = s_esq_u[p0 + 3];
            unsigned long long a10 = a00, a11 = a01, a12 = a02, a13 = a03;

#pragma unroll
            for (int d = 0; d < DDIM; d++) {
                const ulonglong2* row = (const ulonglong2*)(s_e + d * KP + p0);
                ulonglong2 t0 = row[0];          // pairs p0+0, p0+1 (LDS.128 broadcast)
                ulonglong2 t1 = row[1];          // pairs p0+2, p0+3
                unsigned long long xa = pack2(x0[d]);
                unsigned long long xb = pack2(x1[d]);
                a00 = ffma2(xa, t0.x, a00);
                a01 = ffma2(xa, t0.y, a01);
                a02 = ffma2(xa, t1.x, a02);
                a03 = ffma2(xa, t1.y, a03);
                a10 = ffma2(xb, t0.x, a10);
                a11 = ffma2(xb, t0.y, a11);
                a12 = ffma2(xb, t1.x, a12);
                a13 = ffma2(xb, t1.y, a13);
            }
            // strict < in increasing code order == first-index argmin tie-break
            int k = 2 * p0;
            float f;
            f = lo32(a00); if (f < best0) { best0 = f; bi0 = k + 0; }
            f = hi32(a00); if (f < best0) { best0 = f; bi0 = k + 1; }
            f = lo32(a01); if (f < best0) { best0 = f; bi0 = k + 2; }
            f = hi32(a01); if (f < best0) { best0 = f; bi0 = k + 3; }
            f = lo32(a02); if (f < best0) { best0 = f; bi0 = k + 4; }
            f = hi32(a02); if (f < best0) { best0 = f; bi0 = k + 5; }
            f = lo32(a03); if (f < best0) { best0 = f; bi0 = k + 6; }
            f = hi32(a03); if (f < best0) { best0 = f; bi0 = k + 7; }

            f = lo32(a10); if (f < best1) { best1 = f; bi1 = k + 0; }
            f = hi32(a10); if (f < best1) { best1 = f; bi1 = k + 1; }
            f = lo32(a11); if (f < best1) { best1 = f; bi1 = k + 2; }
            f = hi32(a11); if (f < best1) { best1 = f; bi1 = k + 3; }
            f = lo32(a12); if (f < best1) { best1 = f; bi1 = k + 4; }
            f = hi32(a12); if (f < best1) { best1 = f; bi1 = k + 5; }
            f = lo32(a13); if (f < best1) { best1 = f; bi1 = k + 6; }
            f = hi32(a13); if (f < best1) { best1 = f; bi1 = k + 7; }
        }

        // ---- gather + write quantized, accumulate loss
        {
            const int pw = bi0 >> 1, hi = bi0 & 1;
            float4* op = (float4*)(out + (size_t)v0 * DDIM);
#pragma unroll
            for (int i = 0; i < DDIM / 4; i++) {
                float4 q;
                float e;
                float2 ee;
                ee = s_e[(4*i+0) * KP + pw]; e = -0.5f * (hi ? ee.y : ee.x); q.x = e;
                { float df = e - x0[4*i+0]; lsum += df * df; }
                ee = s_e[(4*i+1) * KP + pw]; e = -0.5f * (hi ? ee.y : ee.x); q.y = e;
                { float df = e - x0[4*i+1]; lsum += df * df; }
                ee = s_e[(4*i+2) * KP + pw]; e = -0.5f * (hi ? ee.y : ee.x); q.z = e;
                { float df = e - x0[4*i+2]; lsum += df * df; }
                ee = s_e[(4*i+3) * KP + pw]; e = -0.5f * (hi ? ee.y : ee.x); q.w = e;
                { float df = e - x0[4*i+3]; lsum += df * df; }
                op[i] = q;
            }
        }
        {
            const int pw = bi1 >> 1, hi = bi1 & 1;
            float4* op = (float4*)(out + (size_t)v1 * DDIM);
#pragma unroll
            for (int i = 0; i < DDIM / 4; i++) {
                float4 q;
                float e;
                float2 ee;
                ee = s_e[(4*i+0) * KP + pw]; e = -0.5f * (hi ? ee.y : ee.x); q.x = e;
                { float df = e - x1[4*i+0]; lsum += df * df; }
                ee = s_e[(4*i+1) * KP + pw]; e = -0.5f * (hi ? ee.y : ee.x); q.y = e;
                { float df = e - x1[4*i+1]; lsum += df * df; }
                ee = s_e[(4*i+2) * KP + pw]; e = -0.5f * (hi ? ee.y : ee.x); q.z = e;
                { float df = e - x1[4*i+2]; lsum += df * df; }
                ee = s_e[(4*i+3) * KP + pw]; e = -0.5f * (hi ? ee.y : ee.x); q.w = e;
                { float df = e - x1[4*i+3]; lsum += df * df; }
                op[i] = q;
            }
        }
        if (out_size >= NTOT + 1 + NVEC) {
            out[NTOT + 1 + v0] = (float)bi0;
            out[NTOT + 1 + v1] = (float)bi1;
        }
    }

    // ---- loss: warp reduce -> one atomicAdd per warp
    double ls = (double)lsum;
#pragma unroll
    for (int off = 16; off > 0; off >>= 1)
        ls += __shfl_down_sync(0xffffffffu, ls, off);
    if (lane == 0) atomicAdd(&g_loss, ls);

    // ---- last block finalizes: write loss scalar, reset all state
    __syncthreads();
    if (tid == 0) {
        __threadfence();
        unsigned done = atomicAdd(&g_done, 1u);
        if (done == GRID - 1) {
            unsigned long long bits =
                atomicExch((unsigned long long*)&g_loss, 0ull);  // read + reset
            double total = __longlong_as_double((long long)bits);
            if (out_size >= NTOT + 1)
                out[NTOT] = (float)(2.0 * total / (double)NTOT);
            atomicExch(&g_unit, 0u);
            atomicExch(&g_done, 0u);
        }
    }
}

extern "C" void kernel_launch(void* const* d_in, const int* in_sizes, int n_in,
                              void* d_out, int out_size) {
    const float* enc   = (const float*)d_in[0];
    const float* embed = (const float*)d_in[1];
    float* out = (float*)d_out;

    static bool attr_set = false;
    if (!attr_set) {
        cudaFuncSetAttribute(vq_kernel,
                             cudaFuncAttributeMaxDynamicSharedMemorySize,
                             SMEM_BYTES);
        attr_set = true;
    }

    vq_kernel<<<GRID, TPB, SMEM_BYTES>>>(enc, embed, out, out_size);
}